// round 14
// baseline (speedup 1.0000x reference)
#include <cuda_runtime.h>
#include <cstdint>

// YOLO loss: pred/target (bs, 7, 7, 30) f32 -> scalar f32.
// Warp-specialized streaming pipeline: warp 4 (lane 0) is a dedicated
// producer running the whole cp.async.bulk issue loop (empty-wait -> fill),
// warps 0-3 are pure consumers (full-wait -> compute -> empty-arrive).
// 3-stage ring, TILE=128, grid-strided tiles, last-block finalize.
// Grid sized for GB300's 152 SMs (2 CTAs/SM -> 304 blocks).

#define S_GRID 7
#define CH 30
#define TILE 128
#define CONSUMERS 128                       // 4 consumer warps
#define NTHREADS 160                        // + 1 producer warp
#define STAGES 3
#define SFLOATS (TILE * CH)                 // 3840 floats per tensor per stage
#define STAGE_FLOATS (2 * SFLOATS)          // 7680 floats (pred + targ)
#define STAGE_BYTES (STAGE_FLOATS * 4)      // 30720 B
#define HALF_BYTES (SFLOATS * 4)            // 15360 B
#define SMEM_BYTES (STAGES * STAGE_BYTES)   // 92160 B -> 2 CTAs/SM
#define MAX_BLOCKS 304                      // 2 * 152 SMs (GB300)

__device__ double g_acc = 0.0;
__device__ unsigned int g_counter = 0u;

__device__ __forceinline__ void mbar_init(uint32_t mbar, uint32_t cnt) {
    asm volatile("mbarrier.init.shared.b64 [%0], %1;" :: "r"(mbar), "r"(cnt) : "memory");
}
__device__ __forceinline__ void mbar_expect_tx(uint32_t mbar, uint32_t bytes) {
    asm volatile("mbarrier.arrive.expect_tx.shared.b64 _, [%0], %1;"
                 :: "r"(mbar), "r"(bytes) : "memory");
}
__device__ __forceinline__ void mbar_arrive(uint32_t mbar) {
    asm volatile("mbarrier.arrive.shared.b64 _, [%0];" :: "r"(mbar) : "memory");
}
__device__ __forceinline__ void mbar_wait(uint32_t mbar, uint32_t parity) {
    asm volatile(
        "{\n\t"
        ".reg .pred P;\n\t"
        "WAIT_%=:\n\t"
        "mbarrier.try_wait.parity.acquire.cta.shared::cta.b64 P, [%0], %1, 0x989680;\n\t"
        "@P bra.uni DONE_%=;\n\t"
        "bra.uni WAIT_%=;\n\t"
        "DONE_%=:\n\t"
        "}" :: "r"(mbar), "r"(parity) : "memory");
}
__device__ __forceinline__ void bulk_g2s(uint32_t dst, const void* src,
                                         uint32_t bytes, uint32_t mbar) {
    asm volatile(
        "cp.async.bulk.shared::cta.global.mbarrier::complete_tx::bytes [%0], [%1], %2, [%3];"
        :: "r"(dst), "l"(src), "r"(bytes), "r"(mbar) : "memory");
}

// Per-cell loss; p/t point at 30 contiguous floats (smem or gmem).
__device__ __forceinline__ float cell_loss(const float* __restrict__ p,
                                           const float* __restrict__ t)
{
    const float obj = (t[4] > 0.0f) ? 1.0f : 0.0f;

    const float dn0 = p[4] - t[4];
    const float dn1 = p[9] - t[9];
    const float noobj = dn0 * dn0 + dn1 * dn1;

    float cls = 0.0f;
    #pragma unroll
    for (int k = 10; k < 30; k++) {
        const float d = p[k] - t[k];
        cls = fmaf(d, d, cls);
    }

    const float invS = 1.0f / (float)S_GRID;
    const float tx = t[0] * invS, ty = t[1] * invS;
    const float tw = t[2], th = t[3];
    const float tx0 = tx - 0.5f * tw, tx1 = tx + 0.5f * tw;
    const float ty0 = ty - 0.5f * th, ty1 = ty + 0.5f * th;
    const float area_t = tw * th;

    float iou0 = 0.0f, iou1 = 0.0f;
    #pragma unroll
    for (int b = 0; b < 2; b++) {
        const float* q = p + 5 * b;
        const float px = q[0] * invS, py = q[1] * invS;
        const float pw = q[2], ph = q[3];
        const float lx = fmaxf(px - 0.5f * pw, tx0);
        const float rx = fminf(px + 0.5f * pw, tx1);
        const float ly = fmaxf(py - 0.5f * ph, ty0);
        const float ry = fminf(py + 0.5f * ph, ty1);
        const float wx = fmaxf(rx - lx, 0.0f);
        const float wy = fmaxf(ry - ly, 0.0f);
        const float inter = wx * wy;
        const float uni = fmaxf(pw * ph + area_t - inter, 1e-10f);
        const float iou = inter / uni;
        if (b == 0) iou0 = iou; else iou1 = iou;
    }
    // jnp.argmax picks first max -> box 1 only on strict greater.
    const int rb = (iou1 > iou0) ? 1 : 0;
    const float miou = fmaxf(iou0, iou1);

    const float* q  = p + 5 * rb;
    const float* tq = t + 5 * rb;
    const float dx = q[0] - tq[0];
    const float dy = q[1] - tq[1];
    const float lxy = dx * dx + dy * dy;
    const float dw = sqrtf(q[2]) - sqrtf(tq[2]);
    const float dh = sqrtf(q[3]) - sqrtf(tq[3]);
    const float lwh = dw * dw + dh * dh;
    const float dob = q[4] - miou;
    const float lobj = dob * dob;

    return obj * (5.0f * (lxy + lwh) + lobj + cls)
         + 0.5f * (1.0f - obj) * noobj;
}

__global__ __launch_bounds__(NTHREADS) void yolo_loss_kernel(
    const float* __restrict__ pred,
    const float* __restrict__ targ,
    int total_cells,
    float* __restrict__ out,
    double inv_bs)
{
    extern __shared__ float smem[];
    __shared__ __align__(8) uint64_t full_mbar[STAGES];
    __shared__ __align__(8) uint64_t empty_mbar[STAGES];
    __shared__ float warp_sums[CONSUMERS / 32];

    const int tid = threadIdx.x;
    const int lane = tid & 31;
    const uint32_t smem_u32 = (uint32_t)__cvta_generic_to_shared(smem);
    const uint32_t full0  = (uint32_t)__cvta_generic_to_shared(full_mbar);
    const uint32_t empty0 = (uint32_t)__cvta_generic_to_shared(empty_mbar);
    const char* predc = (const char*)pred;
    const char* targc = (const char*)targ;

    const int ntiles = total_cells / TILE;
    const int rem = total_cells - ntiles * TILE;
    const long long stride = gridDim.x;
    const long long t0 = blockIdx.x;

    if (tid == 0) {
        #pragma unroll
        for (int s = 0; s < STAGES; s++) {
            mbar_init(full0  + 8u * s, 1u);             // producer expect_tx
            mbar_init(empty0 + 8u * s, CONSUMERS / 32); // one arrive per consumer warp
        }
    }
    __syncthreads();

    float loss = 0.0f;

    if (tid >= CONSUMERS) {
        // ── Producer warp (warp 4). Lane 0 runs the whole issue loop, racing
        // up to STAGES tiles ahead of the consumers.
        if (lane == 0) {
            long long k = 0;
            for (long long t = t0; t < ntiles; t += stride, k++) {
                const int s = (int)(k % STAGES);
                const long long c = k / STAGES;   // fill count for this stage
                if (c > 0) {
                    // Wait for consumers to drain the previous tile in s.
                    mbar_wait(empty0 + 8u * s, (uint32_t)((c - 1) & 1));
                }
                const uint32_t dst = smem_u32 + (uint32_t)s * STAGE_BYTES;
                mbar_expect_tx(full0 + 8u * s, STAGE_BYTES);
                bulk_g2s(dst,              predc + t * (long long)HALF_BYTES,
                         HALF_BYTES, full0 + 8u * s);
                bulk_g2s(dst + HALF_BYTES, targc + t * (long long)HALF_BYTES,
                         HALF_BYTES, full0 + 8u * s);
            }
        }
    } else {
        // ── Consumer warps (0-3).
        long long k = 0;
        for (long long t = t0; t < ntiles; t += stride, k++) {
            const int s = (int)(k % STAGES);
            const long long c = k / STAGES;

            mbar_wait(full0 + 8u * s, (uint32_t)(c & 1));

            const float* p  = smem + s * STAGE_FLOATS + tid * CH;
            const float* tt = smem + s * STAGE_FLOATS + SFLOATS + tid * CH;
            loss += cell_loss(p, tt);

            __syncwarp();
            if (lane == 0) mbar_arrive(empty0 + 8u * s);
        }

        // Tail cells (total_cells % TILE; zero at bench shape), block 0.
        if (rem && blockIdx.x == 0 && tid < rem) {
            const long long cc = (long long)ntiles * TILE + tid;
            loss += cell_loss(pred + cc * CH, targ + cc * CH);
        }
    }

    // Reduction: consumer warps reduce; producer warp contributes nothing.
    #pragma unroll
    for (int o = 16; o > 0; o >>= 1)
        loss += __shfl_xor_sync(0xffffffffu, loss, o);
    if (tid < CONSUMERS && lane == 0) warp_sums[tid >> 5] = loss;
    __syncthreads();

    if (tid == 0) {
        const float bsum = warp_sums[0] + warp_sums[1] + warp_sums[2] + warp_sums[3];
        atomicAdd(&g_acc, (double)bsum);
        __threadfence();
        const unsigned int ticket = atomicAdd(&g_counter, 1u);
        if (ticket == gridDim.x - 1u) {
            const double total = atomicAdd(&g_acc, 0.0);
            out[0] = (float)(total * inv_bs);
            g_acc = 0.0;          // reset for next graph replay
            __threadfence();
            g_counter = 0u;
        }
    }
}

extern "C" void kernel_launch(void* const* d_in, const int* in_sizes, int n_in,
                              void* d_out, int out_size) {
    const float* pred = (const float*)d_in[0];
    const float* targ = (const float*)d_in[1];
    const long long n = (long long)in_sizes[0];
    const int total_cells = (int)(n / CH);            // bs * 49
    const int bs = total_cells / (S_GRID * S_GRID);
    const int ntiles = total_cells / TILE;

    int grid = ntiles < MAX_BLOCKS ? ntiles : MAX_BLOCKS;
    if (grid < 1) grid = 1;

    cudaFuncSetAttribute(yolo_loss_kernel,
                         cudaFuncAttributeMaxDynamicSharedMemorySize, SMEM_BYTES);
    yolo_loss_kernel<<<grid, NTHREADS, SMEM_BYTES>>>(pred, targ, total_cells,
                                                     (float*)d_out,
                                                     1.0 / (double)bs);
}